// round 15
// baseline (speedup 1.0000x reference)
#include <cuda_runtime.h>

// MeshFit update_points_feat: per-class exact kNN (K=3) + softmax-weighted
// feature gather. C=4, N=4096, M=4096, D=32. Output (1, C*M, D) float32.
//
// R15 = R14 search logic (16x16 grid, 8 lanes/query, u64 packed (dist,idx)
// keys = exact lexicographic top_k, merged 3x3 phase + shells) with:
//  (1) TB=512 + __launch_bounds__(512,3) -> reg cap 42, 3 blocks/SM,
//      occupancy 46% -> ~72%;
//  (2) prep as ONE 64-block kernel: every block redundantly histograms its
//      class (smem atomics) + warp-scans, scatters only its 1/8 slice via
//      global atomic fill counters. Counters are zero at module load and
//      re-zeroed by the query kernel each launch (prep -> query -> next
//      prep is stream-ordered) -> deterministic each replay. Within-cell
//      order nondeterminism is harmless: u64 lex selection is
//      order-invariant => exact jax.lax.top_k semantics, identical output.

#define CC    4
#define NV    4096
#define MV    4096
#define DF    32
#define GW    16
#define NCELL (GW * GW)
#define CELLW (1.0f / GW)
#define QL    8
#define TB    512
#define QPB   (TB / QL)            // 64 queries per block
#define NBLK  ((CC * MV) / QPB)    // 256 blocks

typedef unsigned long long u64;

__device__ float4 g_binned[CC][NV];           // (x, y, z, idx) in bin order
__device__ int    g_cellStart[CC][NCELL + 1];
__device__ int    g_qorder[CC][MV];           // query ids sorted by cell
__device__ int    g_fill[2][CC][NCELL];       // scatter cursors (see header)

__device__ __forceinline__ int clampg(int v) {
    return v < 0 ? 0 : (v > GW - 1 ? GW - 1 : v);
}

// Branchless sorted-top-3 insert on packed (dist,idx) keys; u64 '<' ==
// exact lexicographic (d asc, idx asc) for non-negative distances.
__device__ __forceinline__ void kins(u64 k, u64& k0, u64& k1, u64& k2)
{
    const bool c0 = k < k0;
    const bool c1 = k < k1;
    const bool c2 = k < k2;
    k2 = c1 ? k1 : (c2 ? k : k2);
    k1 = c0 ? k0 : (c1 ? k : k1);
    k0 = c0 ? k  : k0;
}

__device__ __forceinline__ float key_d(u64 k) {
    return __uint_as_float((unsigned)(k >> 32));
}
__device__ __forceinline__ int key_i(u64 k) {
    return (int)(unsigned)k;
}

// ---- K1: bin points + sort queries (64 blocks, redundant histogram) ------
__global__ void __launch_bounds__(512, 2)
prep_kernel(const float* __restrict__ verts,
            const float* __restrict__ nverts)
{
    __shared__ int cnt[NCELL];
    __shared__ int ex[NCELL];
    const int b    = blockIdx.x;               // 64 blocks
    const int role = b & 1;                    // 0: points, 1: queries
    const int c    = (b >> 1) & 3;
    const int seg  = b >> 3;                   // 0..7
    const int tid  = threadIdx.x;
    const float* src = role ? (nverts + (size_t)c * MV * 3)
                            : (verts + (size_t)c * NV * 3);

    if (tid < NCELL) cnt[tid] = 0;
    __syncthreads();

    // Full-class histogram (redundant across the 8 segs of this class/role).
    for (int n = tid; n < NV; n += 512) {
        const int cx = clampg((int)(src[3 * n + 0] * GW));
        const int cy = clampg((int)(src[3 * n + 1] * GW));
        atomicAdd(&cnt[cy * GW + cx], 1);
    }
    __syncthreads();

    // One warp computes the exclusive prefix over 256 cells.
    if (tid < 32) {
        const int base = tid * 8;
        int v[8], run = 0;
#pragma unroll
        for (int j = 0; j < 8; ++j) { v[j] = run; run += cnt[base + j]; }
        int inc = run;
#pragma unroll
        for (int off = 1; off < 32; off <<= 1) {
            const int nb = __shfl_up_sync(0xffffffffu, inc, off);
            if (tid >= off) inc += nb;
        }
        const int pre = inc - run;             // exclusive prefix of lane
#pragma unroll
        for (int j = 0; j < 8; ++j) ex[base + j] = pre + v[j];
    }
    __syncthreads();

    if (!role && seg == 0) {
        if (tid < NCELL) g_cellStart[c][tid] = ex[tid];
        if (tid == 0)    g_cellStart[c][NCELL] = NV;
    }

    // Scatter only this block's 1/8 slice (512 items, one per thread).
    {
        const int n = seg * 512 + tid;
        const float x = src[3 * n + 0], y = src[3 * n + 1];
        const int cell = clampg((int)(y * GW)) * GW + clampg((int)(x * GW));
        const int slot = ex[cell] + atomicAdd(&g_fill[role][c][cell], 1);
        if (role) g_qorder[c][slot] = n;
        else      g_binned[c][slot] = make_float4(x, y, src[3 * n + 2],
                                                  __int_as_float(n));
    }
}

// Scan a contiguous slot range [s, e) with the group's 8 lanes.
__device__ __forceinline__ void scan_range(const float4* __restrict__ spts,
                                           int s, int e, int lq,
                                           float qx, float qy, float qz,
                                           u64& k0, u64& k1, u64& k2)
{
    for (int p = s + lq; p < e; p += QL) {
        const float4 pt = spts[p];
        const float dx = qx - pt.x;
        const float dy = qy - pt.y;
        const float dz = qz - pt.z;
        const float t = fmaf(dz, dz, fmaf(dy, dy, dx * dx));
        const u64 k = ((u64)__float_as_uint(t) << 32)
                    | (u64)(unsigned)__float_as_int(pt.w);
        kins(k, k0, k1, k2);
    }
}

// ---- K2: per-group search: merged 3x3 block, then shells ----------------
__global__ void __launch_bounds__(TB, 3)
query_kernel(const float* __restrict__ feat,
             const float* __restrict__ nverts,
             float* __restrict__ out)
{
    extern __shared__ char smem[];
    float4* spts   = (float4*)smem;                      // 64 KB
    int*    sStart = (int*)(smem + NV * sizeof(float4)); // 257 ints

    const int tid = threadIdx.x;
    const int lq  = tid & (QL - 1);
    const int c    = blockIdx.x >> 6;          // 64 blocks per class
    const int slot = (blockIdx.x & 63) * QPB + (tid >> 3);

    // Re-zero scatter cursors for the NEXT launch (this kernel never reads
    // them; prep of the next replay runs after this kernel completes).
    if (blockIdx.x == 0) {
        int* f = &g_fill[0][0][0];
        for (int i = tid; i < 2 * CC * NCELL; i += TB) f[i] = 0;
    }

    // Stage this class's binned points + cell table.
    for (int i = tid; i < NV; i += TB) spts[i] = g_binned[c][i];
    for (int i = tid; i < NCELL + 1; i += TB) sStart[i] = g_cellStart[c][i];
    __syncthreads();

    const int m = g_qorder[c][slot];
    const float* q = nverts + ((size_t)c * MV + m) * 3;
    const float qx = q[0], qy = q[1], qz = q[2];
    const int cx = clampg((int)(qx * GW));
    const int cy = clampg((int)(qy * GW));

    u64 k0 = 0x7F800000FFFFFFFFull;   // (+inf, idx_max)
    u64 k1 = 0x7F800000FFFFFFFFull;
    u64 k2 = 0x7F800000FFFFFFFFull;

    // Phase 1: merged rings 0+1 = the 3x3 cell block, as contiguous rows.
    {
        const int x0 = cx - 1 < 0 ? 0 : cx - 1;
        const int x1 = cx + 1 > GW - 1 ? GW - 1 : cx + 1;
        const int y0 = cy - 1 < 0 ? 0 : cy - 1;
        const int y1 = cy + 1 > GW - 1 ? GW - 1 : cy + 1;
#pragma unroll 1
        for (int Y = y0; Y <= y1; ++Y) {
            const int cb = Y * GW;
            scan_range(spts, sStart[cb + x0], sStart[cb + x1 + 1], lq,
                       qx, qy, qz, k0, k1, k2);
        }
    }

    // Stop check after the 3x3 block (covered square = rings 0..1).
    bool done;
    {
        float B = key_d(k2);
#pragma unroll
        for (int off = 1; off < QL; off <<= 1)
            B = fminf(B, __shfl_xor_sync(0xffffffffu, B, off));
        const float sL = (cx - 1 <= 0)      ? 1e30f : qx - (cx - 1) * CELLW;
        const float sR = (cx + 1 >= GW - 1) ? 1e30f : (cx + 2) * CELLW - qx;
        const float sB = (cy - 1 <= 0)      ? 1e30f : qy - (cy - 1) * CELLW;
        const float sT = (cy + 1 >= GW - 1) ? 1e30f : (cy + 2) * CELLW - qy;
        const float dmin = fminf(fminf(sL, sR), fminf(sB, sT));
        done = (B * 1.00001f < dmin * dmin);
    }

    // Phase 2: expanding shells for r >= 2.
    if (!__all_sync(0xffffffffu, done)) {
#pragma unroll 1
        for (int r = 2; r < GW; ++r) {
            if (!done) {
                const int x0 = cx - r < 0 ? 0 : cx - r;
                const int x1 = cx + r > GW - 1 ? GW - 1 : cx + r;
                if (cy - r >= 0) {
                    const int cb = (cy - r) * GW;
                    scan_range(spts, sStart[cb + x0], sStart[cb + x1 + 1], lq,
                               qx, qy, qz, k0, k1, k2);
                }
                if (cy + r <= GW - 1) {
                    const int cb = (cy + r) * GW;
                    scan_range(spts, sStart[cb + x0], sStart[cb + x1 + 1], lq,
                               qx, qy, qz, k0, k1, k2);
                }
                const int ym0 = cy - r + 1 < 0 ? 0 : cy - r + 1;
                const int ym1 = cy + r - 1 > GW - 1 ? GW - 1 : cy + r - 1;
#pragma unroll 1
                for (int Y = ym0; Y <= ym1; ++Y) {
                    const int cb = Y * GW;
                    if (cx - r >= 0)
                        scan_range(spts, sStart[cb + cx - r],
                                   sStart[cb + cx - r + 1], lq,
                                   qx, qy, qz, k0, k1, k2);
                    if (cx + r <= GW - 1)
                        scan_range(spts, sStart[cb + cx + r],
                                   sStart[cb + cx + r + 1], lq,
                                   qx, qy, qz, k0, k1, k2);
                }
            }
            float B = key_d(k2);
#pragma unroll
            for (int off = 1; off < QL; off <<= 1)
                B = fminf(B, __shfl_xor_sync(0xffffffffu, B, off));
            const float sL = (cx - r <= 0)      ? 1e30f : qx - (cx - r) * CELLW;
            const float sR = (cx + r >= GW - 1) ? 1e30f : (cx + r + 1) * CELLW - qx;
            const float sB = (cy - r <= 0)      ? 1e30f : qy - (cy - r) * CELLW;
            const float sT = (cy + r >= GW - 1) ? 1e30f : (cy + r + 1) * CELLW - qy;
            const float dmin = fminf(fminf(sL, sR), fminf(sB, sT));
            done = done || (B * 1.00001f < dmin * dmin);
            if (__all_sync(0xffffffffu, done)) break;
        }
    }

    // Butterfly merge across the 8 lanes of this group (exact lex order).
#pragma unroll
    for (int off = 1; off < QL; off <<= 1) {
        const u64 p0 = __shfl_xor_sync(0xffffffffu, k0, off);
        const u64 p1 = __shfl_xor_sync(0xffffffffu, k1, off);
        const u64 p2 = __shfl_xor_sync(0xffffffffu, k2, off);
        kins(p0, k0, k1, k2);
        kins(p1, k0, k1, k2);
        kins(p2, k0, k1, k2);
    }

    // Local -> global column index (low-word add; no carry possible), then
    // exact merge of the constant-1.0 off-block fillers.
    const u64 base = (u64)(c * NV);
    k0 += base; k1 += base; k2 += base;
    const unsigned fbase = (c == 0) ? NV : 0;
#pragma unroll
    for (int k = 0; k < 3; ++k)
        kins(((u64)0x3F800000u << 32) | (u64)(fbase + k), k0, k1, k2);

    const float d0 = key_d(k0), d1 = key_d(k1), d2 = key_d(k2);
    const int   g0 = key_i(k0), g1 = key_i(k1), g2 = key_i(k2);

    // softmax(-d), max-subtracted (d0 smallest).
    const float e1 = expf(d0 - d1);
    const float e2 = expf(d0 - d2);
    const float inv = 1.0f / (1.0f + e1 + e2);
    const float w0 = inv, w1 = e1 * inv, w2 = e2 * inv;

    // All 8 lanes hold the identical top-3; each writes one float4 chunk.
    const float4 a  = __ldg(&((const float4*)(feat + (size_t)g0 * DF))[lq]);
    const float4 b  = __ldg(&((const float4*)(feat + (size_t)g1 * DF))[lq]);
    const float4 cv = __ldg(&((const float4*)(feat + (size_t)g2 * DF))[lq]);
    float4 rr;
    rr.x = w0 * a.x + w1 * b.x + w2 * cv.x;
    rr.y = w0 * a.y + w1 * b.y + w2 * cv.y;
    rr.z = w0 * a.z + w1 * b.z + w2 * cv.z;
    rr.w = w0 * a.w + w1 * b.w + w2 * cv.w;
    ((float4*)(out + ((size_t)c * MV + m) * DF))[lq] = rr;
}

extern "C" void kernel_launch(void* const* d_in, const int* in_sizes, int n_in,
                              void* d_out, int out_size)
{
    const float* feat   = (const float*)d_in[0];  // (1, C*N, D)
    const float* verts  = (const float*)d_in[1];  // (C, N, 3)
    const float* nverts = (const float*)d_in[2];  // (C, M, 3)
    float* out = (float*)d_out;                   // (1, C*M, D)

    prep_kernel<<<64, 512>>>(verts, nverts);

    const int smem = NV * sizeof(float4) + (NCELL + 1) * sizeof(int);
    cudaFuncSetAttribute(query_kernel,
                         cudaFuncAttributeMaxDynamicSharedMemorySize, smem);
    query_kernel<<<NBLK, TB, smem>>>(feat, nverts, out);
}

// round 17
// speedup vs baseline: 1.1332x; 1.1332x over previous
#include <cuda_runtime.h>

// MeshFit update_points_feat: per-class exact kNN (K=3) + softmax-weighted
// feature gather. C=4, N=4096, M=4096, D=32. Output (1, C*M, D) float32.
//
// R17 = R14 search (16x16 grid, 8 lanes/query, u64 packed (dist,idx) keys =
// exact lexicographic top_k, merged 3x3 phase + shells, 128x1024) + TRUE-d2
// STOP BOUND computed on BY-VALUE COPIES: the stop check butterfly-merges
// copies of the lane triples (group_true_d2) so per-lane accumulators stay
// pristine (only their own disjoint candidate stream -> no duplicate keys,
// the R16 bug). The single real merge happens once at the end on
// disjoint-key triples (R14-proven). Prep = R15's 64-block kernel.

#define CC    4
#define NV    4096
#define MV    4096
#define DF    32
#define GW    16
#define NCELL (GW * GW)
#define CELLW (1.0f / GW)
#define QL    8
#define TB    1024
#define QPB   (TB / QL)            // 128 queries per block
#define NBLK  ((CC * MV) / QPB)    // 128 blocks

typedef unsigned long long u64;

__device__ float4 g_binned[CC][NV];           // (x, y, z, idx) in bin order
__device__ int    g_cellStart[CC][NCELL + 1];
__device__ int    g_qorder[CC][MV];           // query ids sorted by cell
__device__ int    g_fill[2][CC][NCELL];       // scatter cursors

__device__ __forceinline__ int clampg(int v) {
    return v < 0 ? 0 : (v > GW - 1 ? GW - 1 : v);
}

// Branchless sorted-top-3 insert on packed (dist,idx) keys; u64 '<' ==
// exact lexicographic (d asc, idx asc) for non-negative distances.
__device__ __forceinline__ void kins(u64 k, u64& k0, u64& k1, u64& k2)
{
    const bool c0 = k < k0;
    const bool c1 = k < k1;
    const bool c2 = k < k2;
    k2 = c1 ? k1 : (c2 ? k : k2);
    k1 = c0 ? k0 : (c1 ? k : k1);
    k0 = c0 ? k  : k0;
}

__device__ __forceinline__ float key_d(u64 k) {
    return __uint_as_float((unsigned)(k >> 32));
}
__device__ __forceinline__ int key_i(u64 k) {
    return (int)(unsigned)k;
}

// TRUE group d2 for the stop check: butterfly-merge BY-VALUE copies of the
// lane triples. Lane accumulators are untouched; all 8 lanes of a group get
// the same result (symmetric butterfly). Copies may accumulate duplicates,
// but the 3rd-smallest of the union is reached monotonically from above, so
// the returned bound is >= true d2 at every intermediate step and == true
// d2 at completion for the purpose of the check... (conservative: we use
// the final merged copy's k2, which equals the union's 3rd-smallest when
// inputs are disjoint per lane — they are, since each point is scanned by
// exactly one lane).
__device__ __forceinline__ float group_true_d2(u64 k0, u64 k1, u64 k2)
{
#pragma unroll
    for (int off = 1; off < QL; off <<= 1) {
        const u64 p0 = __shfl_xor_sync(0xffffffffu, k0, off);
        const u64 p1 = __shfl_xor_sync(0xffffffffu, k1, off);
        const u64 p2 = __shfl_xor_sync(0xffffffffu, k2, off);
        kins(p0, k0, k1, k2);
        kins(p1, k0, k1, k2);
        kins(p2, k0, k1, k2);
    }
    return key_d(k2);
}

// ---- K1: bin points + sort queries (64 blocks, redundant histogram) ------
__global__ void __launch_bounds__(512, 2)
prep_kernel(const float* __restrict__ verts,
            const float* __restrict__ nverts)
{
    __shared__ int cnt[NCELL];
    __shared__ int ex[NCELL];
    const int b    = blockIdx.x;               // 64 blocks
    const int role = b & 1;                    // 0: points, 1: queries
    const int c    = (b >> 1) & 3;
    const int seg  = b >> 3;                   // 0..7
    const int tid  = threadIdx.x;
    const float* src = role ? (nverts + (size_t)c * MV * 3)
                            : (verts + (size_t)c * NV * 3);

    if (tid < NCELL) cnt[tid] = 0;
    __syncthreads();

    for (int n = tid; n < NV; n += 512) {
        const int cx = clampg((int)(src[3 * n + 0] * GW));
        const int cy = clampg((int)(src[3 * n + 1] * GW));
        atomicAdd(&cnt[cy * GW + cx], 1);
    }
    __syncthreads();

    if (tid < 32) {
        const int base = tid * 8;
        int v[8], run = 0;
#pragma unroll
        for (int j = 0; j < 8; ++j) { v[j] = run; run += cnt[base + j]; }
        int inc = run;
#pragma unroll
        for (int off = 1; off < 32; off <<= 1) {
            const int nb = __shfl_up_sync(0xffffffffu, inc, off);
            if (tid >= off) inc += nb;
        }
        const int pre = inc - run;
#pragma unroll
        for (int j = 0; j < 8; ++j) ex[base + j] = pre + v[j];
    }
    __syncthreads();

    if (!role && seg == 0) {
        if (tid < NCELL) g_cellStart[c][tid] = ex[tid];
        if (tid == 0)    g_cellStart[c][NCELL] = NV;
    }

    {
        const int n = seg * 512 + tid;
        const float x = src[3 * n + 0], y = src[3 * n + 1];
        const int cell = clampg((int)(y * GW)) * GW + clampg((int)(x * GW));
        const int slot = ex[cell] + atomicAdd(&g_fill[role][c][cell], 1);
        if (role) g_qorder[c][slot] = n;
        else      g_binned[c][slot] = make_float4(x, y, src[3 * n + 2],
                                                  __int_as_float(n));
    }
}

// Scan a contiguous slot range [s, e) with the group's 8 lanes.
__device__ __forceinline__ void scan_range(const float4* __restrict__ spts,
                                           int s, int e, int lq,
                                           float qx, float qy, float qz,
                                           u64& k0, u64& k1, u64& k2)
{
    for (int p = s + lq; p < e; p += QL) {
        const float4 pt = spts[p];
        const float dx = qx - pt.x;
        const float dy = qy - pt.y;
        const float dz = qz - pt.z;
        const float t = fmaf(dz, dz, fmaf(dy, dy, dx * dx));
        const u64 k = ((u64)__float_as_uint(t) << 32)
                    | (u64)(unsigned)__float_as_int(pt.w);
        kins(k, k0, k1, k2);
    }
}

// ---- K2: per-group search: merged 3x3 block, then shells ----------------
__global__ void __launch_bounds__(TB, 1)
query_kernel(const float* __restrict__ feat,
             const float* __restrict__ nverts,
             float* __restrict__ out)
{
    extern __shared__ char smem[];
    float4* spts   = (float4*)smem;                      // 64 KB
    int*    sStart = (int*)(smem + NV * sizeof(float4)); // 257 ints

    const int tid = threadIdx.x;
    const int lq  = tid & (QL - 1);
    const int c    = blockIdx.x >> 5;          // 32 blocks per class
    const int slot = (blockIdx.x & 31) * QPB + (tid >> 3);

    // Re-zero scatter cursors for the NEXT launch (never read here).
    if (blockIdx.x == 0) {
        int* f = &g_fill[0][0][0];
        for (int i = tid; i < 2 * CC * NCELL; i += TB) f[i] = 0;
    }

    // Stage this class's binned points + cell table.
    for (int i = tid; i < NV; i += TB) spts[i] = g_binned[c][i];
    for (int i = tid; i < NCELL + 1; i += TB) sStart[i] = g_cellStart[c][i];
    __syncthreads();

    const int m = g_qorder[c][slot];
    const float* q = nverts + ((size_t)c * MV + m) * 3;
    const float qx = q[0], qy = q[1], qz = q[2];
    const int cx = clampg((int)(qx * GW));
    const int cy = clampg((int)(qy * GW));

    u64 k0 = 0x7F800000FFFFFFFFull;   // (+inf, idx_max)
    u64 k1 = 0x7F800000FFFFFFFFull;
    u64 k2 = 0x7F800000FFFFFFFFull;

    // Phase 1: merged rings 0+1 = the 3x3 cell block, as contiguous rows.
    {
        const int x0 = cx - 1 < 0 ? 0 : cx - 1;
        const int x1 = cx + 1 > GW - 1 ? GW - 1 : cx + 1;
        const int y0 = cy - 1 < 0 ? 0 : cy - 1;
        const int y1 = cy + 1 > GW - 1 ? GW - 1 : cy + 1;
#pragma unroll 1
        for (int Y = y0; Y <= y1; ++Y) {
            const int cb = Y * GW;
            scan_range(spts, sStart[cb + x0], sStart[cb + x1 + 1], lq,
                       qx, qy, qz, k0, k1, k2);
        }
    }

    // Stop check with TRUE group d2 (merge on copies; accumulators clean).
    bool done;
    {
        const float B = group_true_d2(k0, k1, k2);
        const float sL = (cx - 1 <= 0)      ? 1e30f : qx - (cx - 1) * CELLW;
        const float sR = (cx + 1 >= GW - 1) ? 1e30f : (cx + 2) * CELLW - qx;
        const float sB = (cy - 1 <= 0)      ? 1e30f : qy - (cy - 1) * CELLW;
        const float sT = (cy + 1 >= GW - 1) ? 1e30f : (cy + 2) * CELLW - qy;
        const float dmin = fminf(fminf(sL, sR), fminf(sB, sT));
        done = (B * 1.00001f < dmin * dmin);
    }

    // Phase 2: expanding shells for r >= 2; true-d2 check per ring.
    if (!__all_sync(0xffffffffu, done)) {
#pragma unroll 1
        for (int r = 2; r < GW; ++r) {
            if (!done) {
                const int x0 = cx - r < 0 ? 0 : cx - r;
                const int x1 = cx + r > GW - 1 ? GW - 1 : cx + r;
                if (cy - r >= 0) {
                    const int cb = (cy - r) * GW;
                    scan_range(spts, sStart[cb + x0], sStart[cb + x1 + 1], lq,
                               qx, qy, qz, k0, k1, k2);
                }
                if (cy + r <= GW - 1) {
                    const int cb = (cy + r) * GW;
                    scan_range(spts, sStart[cb + x0], sStart[cb + x1 + 1], lq,
                               qx, qy, qz, k0, k1, k2);
                }
                const int ym0 = cy - r + 1 < 0 ? 0 : cy - r + 1;
                const int ym1 = cy + r - 1 > GW - 1 ? GW - 1 : cy + r - 1;
#pragma unroll 1
                for (int Y = ym0; Y <= ym1; ++Y) {
                    const int cb = Y * GW;
                    if (cx - r >= 0)
                        scan_range(spts, sStart[cb + cx - r],
                                   sStart[cb + cx - r + 1], lq,
                                   qx, qy, qz, k0, k1, k2);
                    if (cx + r <= GW - 1)
                        scan_range(spts, sStart[cb + cx + r],
                                   sStart[cb + cx + r + 1], lq,
                                   qx, qy, qz, k0, k1, k2);
                }
            }
            const float B = group_true_d2(k0, k1, k2);   // warp-synchronous
            const float sL = (cx - r <= 0)      ? 1e30f : qx - (cx - r) * CELLW;
            const float sR = (cx + r >= GW - 1) ? 1e30f : (cx + r + 1) * CELLW - qx;
            const float sB = (cy - r <= 0)      ? 1e30f : qy - (cy - r) * CELLW;
            const float sT = (cy + r >= GW - 1) ? 1e30f : (cy + r + 1) * CELLW - qy;
            const float dmin = fminf(fminf(sL, sR), fminf(sB, sT));
            done = done || (B * 1.00001f < dmin * dmin);
            if (__all_sync(0xffffffffu, done)) break;
        }
    }

    // The ONE real merge, on disjoint-key lane triples (R14-proven exact).
#pragma unroll
    for (int off = 1; off < QL; off <<= 1) {
        const u64 p0 = __shfl_xor_sync(0xffffffffu, k0, off);
        const u64 p1 = __shfl_xor_sync(0xffffffffu, k1, off);
        const u64 p2 = __shfl_xor_sync(0xffffffffu, k2, off);
        kins(p0, k0, k1, k2);
        kins(p1, k0, k1, k2);
        kins(p2, k0, k1, k2);
    }

    // Local -> global column index (low-word add; no carry possible), then
    // exact merge of the constant-1.0 off-block fillers.
    const u64 base = (u64)(c * NV);
    k0 += base; k1 += base; k2 += base;
    const unsigned fbase = (c == 0) ? NV : 0;
#pragma unroll
    for (int k = 0; k < 3; ++k)
        kins(((u64)0x3F800000u << 32) | (u64)(fbase + k), k0, k1, k2);

    const float d0 = key_d(k0), d1 = key_d(k1), d2 = key_d(k2);
    const int   g0 = key_i(k0), g1 = key_i(k1), g2 = key_i(k2);

    // softmax(-d), max-subtracted (d0 smallest).
    const float e1 = expf(d0 - d1);
    const float e2 = expf(d0 - d2);
    const float inv = 1.0f / (1.0f + e1 + e2);
    const float w0 = inv, w1 = e1 * inv, w2 = e2 * inv;

    // All 8 lanes hold the identical top-3; each writes one float4 chunk.
    const float4 a  = __ldg(&((const float4*)(feat + (size_t)g0 * DF))[lq]);
    const float4 b  = __ldg(&((const float4*)(feat + (size_t)g1 * DF))[lq]);
    const float4 cv = __ldg(&((const float4*)(feat + (size_t)g2 * DF))[lq]);
    float4 rr;
    rr.x = w0 * a.x + w1 * b.x + w2 * cv.x;
    rr.y = w0 * a.y + w1 * b.y + w2 * cv.y;
    rr.z = w0 * a.z + w1 * b.z + w2 * cv.z;
    rr.w = w0 * a.w + w1 * b.w + w2 * cv.w;
    ((float4*)(out + ((size_t)c * MV + m) * DF))[lq] = rr;
}

extern "C" void kernel_launch(void* const* d_in, const int* in_sizes, int n_in,
                              void* d_out, int out_size)
{
    const float* feat   = (const float*)d_in[0];  // (1, C*N, D)
    const float* verts  = (const float*)d_in[1];  // (C, N, 3)
    const float* nverts = (const float*)d_in[2];  // (C, M, 3)
    float* out = (float*)d_out;                   // (1, C*M, D)

    prep_kernel<<<64, 512>>>(verts, nverts);

    const int smem = NV * sizeof(float4) + (NCELL + 1) * sizeof(int);
    cudaFuncSetAttribute(query_kernel,
                         cudaFuncAttributeMaxDynamicSharedMemorySize, smem);
    query_kernel<<<NBLK, TB, smem>>>(feat, nverts, out);
}